// round 16
// baseline (speedup 1.0000x reference)
#include <cuda_runtime.h>
#include <cuda_fp16.h>
#include <math.h>
#include <stdint.h>

// Problem constants
#define BATCH 2
#define SEQ   2048
#define CDIM  1024
#define NHEAD 16
#define HDIM  64
#define ROWS  (BATCH * SEQ)          // 4096
#define HID   (4 * CDIM)             // 4096

typedef unsigned short u16;
typedef unsigned int   u32;

// ---------------- scratch (static device globals; no allocation) ----------------
__device__ float g_t  [(size_t)ROWS * CDIM];
__device__ float g_x1 [(size_t)ROWS * CDIM];
__device__ u16 g_xh  [(size_t)ROWS * CDIM];
__device__ u16 g_qkvh[(size_t)ROWS * 3 * CDIM];
__device__ u16 g_yh  [(size_t)ROWS * CDIM];
__device__ u16 g_x1h [(size_t)ROWS * CDIM];
__device__ u16 g_hh  [(size_t)ROWS * HID];
// transposed fp16 weights, layout [N][K]
__device__ u16 g_wa[(size_t)3*CDIM*CDIM];
__device__ u16 g_w1[(size_t)HID*CDIM];
__device__ u16 g_w2[(size_t)CDIM*HID];
__device__ u16 g_w3[(size_t)HID*CDIM];
__device__ u16 g_w4[(size_t)CDIM*HID];

// ---------------- helpers ----------------
__device__ __forceinline__ uint32_t smem_u32(const void* p) {
    uint32_t a;
    asm("{ .reg .u64 t; cvta.to.shared.u64 t, %1; cvt.u32.u64 %0, t; }" : "=r"(a) : "l"(p));
    return a;
}
__device__ __forceinline__ void cp16(uint32_t dst, const void* src) {
    asm volatile("cp.async.cg.shared.global [%0], [%1], 16;" :: "r"(dst), "l"(src) : "memory");
}
#define CP_COMMIT() asm volatile("cp.async.commit_group;" ::: "memory")
#define CP_WAIT(n)  asm volatile("cp.async.wait_group %0;" :: "n"(n) : "memory")

__device__ __forceinline__ void ldsm4(u32* r, u32 addr) {
    asm volatile("ldmatrix.sync.aligned.m8n8.x4.shared.b16 {%0,%1,%2,%3}, [%4];"
        : "=r"(r[0]), "=r"(r[1]), "=r"(r[2]), "=r"(r[3]) : "r"(addr));
}
__device__ __forceinline__ void ldsm4t(u32* r, u32 addr) {
    asm volatile("ldmatrix.sync.aligned.m8n8.x4.trans.shared.b16 {%0,%1,%2,%3}, [%4];"
        : "=r"(r[0]), "=r"(r[1]), "=r"(r[2]), "=r"(r[3]) : "r"(addr));
}
__device__ __forceinline__ void mma_fp16(float* d, const u32* a, const u32* b) {
    asm volatile("mma.sync.aligned.m16n8k16.row.col.f32.f16.f16.f32 "
        "{%0,%1,%2,%3}, {%4,%5,%6,%7}, {%8,%9}, {%0,%1,%2,%3};"
        : "+f"(d[0]), "+f"(d[1]), "+f"(d[2]), "+f"(d[3])
        : "r"(a[0]), "r"(a[1]), "r"(a[2]), "r"(a[3]), "r"(b[0]), "r"(b[1]));
}
__device__ __forceinline__ uint32_t swz(uint32_t off) { return off ^ ((off >> 3) & 0x70); }

__device__ __forceinline__ u16 fp_hi(float v) { return __half_as_ushort(__float2half_rn(v)); }

// ---------------- convert activations: fp32 -> fp16 ----------------
__global__ __launch_bounds__(256) void conv_k(const float* __restrict__ x,
                                              u16* __restrict__ h, int n4) {
    int i = blockIdx.x * 256 + threadIdx.x;
    if (i >= n4) return;
    float4 v = ((const float4*)x)[i];
    u16 h0 = fp_hi(v.x), h1 = fp_hi(v.y), h2 = fp_hi(v.z), h3 = fp_hi(v.w);
    ((uint2*)h)[i] = make_uint2((u32)h0 | ((u32)h1 << 16), (u32)h2 | ((u32)h3 << 16));
}

// ---------------- transpose weights: W[K][N] fp32 -> T[N][K] fp16 ----------------
__global__ __launch_bounds__(256) void tdecomp_k(const float* __restrict__ W,
                                                 u16* __restrict__ Th, int K, int N) {
    __shared__ float t[32][33];
    const int n0 = blockIdx.x * 32, k0 = blockIdx.y * 32;
    const int tx = threadIdx.x, ty = threadIdx.y;  // 32x8
    #pragma unroll
    for (int i = 0; i < 32; i += 8)
        t[ty + i][tx] = W[(size_t)(k0 + ty + i) * N + n0 + tx];
    __syncthreads();
    #pragma unroll
    for (int i = 0; i < 32; i += 8) {
        float v = t[tx][ty + i];
        Th[(size_t)(n0 + ty + i) * K + k0 + tx] = fp_hi(v);
    }
}

// ---------------- tensor-core GEMM via mma.sync (fp16, 1-term) ----------------
// C = A @ B^T (+bias).  OUT=0: fp32 C. OUT=1: gelu -> fp16. OUT=2: fp16 (no gelu).
// BK=64, 3-stage cp.async ring, SINGLE __syncthreads per chunk.
// 96KB smem/CTA -> still 2 CTAs/SM (192 <= 227KB).
#define BK 64
#define STAGE_B 32768
#define MG_SMEM (3 * STAGE_B)   // 96 KB

template<int OUT>
__global__ __launch_bounds__(256, 2) void mma_gemm(
    const u16* __restrict__ A, const u16* __restrict__ B,
    const float* __restrict__ bias,
    float* __restrict__ C, u16* __restrict__ Ch,
    int N, int K)
{
    extern __shared__ char smem_raw[];
    const uint32_t sbase = smem_u32(smem_raw);

    const int tid = threadIdx.x, lane = tid & 31, wid = tid >> 5;
    const int warp_m = wid & 3, warp_n = wid >> 2;
    const int bm = blockIdx.y * 128, bn = blockIdx.x * 128;

    const u16* aP = A + (size_t)bm * K;
    const u16* bP = B + (size_t)bn * K;

    const int nk = K / BK;

    auto load_stage = [&](int t) {
        const uint32_t st = sbase + (uint32_t)(t % 3) * STAGE_B;
        const int k0 = t * BK;
        #pragma unroll
        for (int i = 0; i < 4; ++i) {
            const int idx = i * 256 + tid;          // 1024 segs per 16KB tile
            const int row = idx >> 3, seg = idx & 7;
            const uint32_t soff = swz((uint32_t)(row * 128 + seg * 16));
            const size_t goff = (size_t)row * K + k0 + seg * 8;
            cp16(st + soff,         aP + goff);
            cp16(st + 16384 + soff, bP + goff);
        }
        CP_COMMIT();
    };

    float acc[2][8][4];
    #pragma unroll
    for (int mi = 0; mi < 2; ++mi)
        #pragma unroll
        for (int ni = 0; ni < 8; ++ni)
            #pragma unroll
            for (int j = 0; j < 4; ++j) acc[mi][ni][j] = 0.f;

    load_stage(0);
    load_stage(1);

    const int lrow = lane & 15;
    const int kblk = lane >> 4;

    for (int t = 0; t < nk; ++t) {
        if (t == nk - 1) CP_WAIT(0); else CP_WAIT(1);
        __syncthreads();                       // also proves compute(t-1) done
        if (t + 2 < nk) load_stage(t + 2);     // targets stage (t-1)%3: safe

        const uint32_t st = sbase + (uint32_t)(t % 3) * STAGE_B;

        #pragma unroll
        for (int s = 0; s < BK / 16; ++s) {
            const int c16 = s * 2 + kblk;
            u32 aa[2][4];
            #pragma unroll
            for (int mi = 0; mi < 2; ++mi) {
                const uint32_t off = swz((uint32_t)((warp_m * 32 + mi * 16 + lrow) * 128 + c16 * 16));
                ldsm4(aa[mi], st + off);
            }
            #pragma unroll
            for (int half = 0; half < 2; ++half) {
                u32 bb[4][2];
                #pragma unroll
                for (int nb = 0; nb < 2; ++nb) {
                    const int nrow = warp_n * 64 + (half * 2 + nb) * 16 + lrow;
                    const uint32_t off = swz((uint32_t)(nrow * 128 + c16 * 16));
                    u32 r[4];
                    ldsm4(r, st + 16384 + off);
                    bb[nb * 2][0] = r[0]; bb[nb * 2 + 1][0] = r[1];
                    bb[nb * 2][1] = r[2]; bb[nb * 2 + 1][1] = r[3];
                }
                #pragma unroll
                for (int mi = 0; mi < 2; ++mi)
                    #pragma unroll
                    for (int nj = 0; nj < 4; ++nj)
                        mma_fp16(acc[mi][half * 4 + nj], aa[mi], bb[nj]);
            }
        }
        // no trailing sync: next iteration's barrier covers stage reuse
    }

    #pragma unroll
    for (int ni = 0; ni < 8; ++ni) {
        const int col = bn + warp_n * 64 + ni * 8 + (lane & 3) * 2;
        const float b0 = bias[col], b1 = bias[col + 1];
        #pragma unroll
        for (int mi = 0; mi < 2; ++mi) {
            const int r0 = bm + warp_m * 32 + mi * 16 + (lane >> 2);
            #pragma unroll
            for (int half = 0; half < 2; ++half) {
                const int r = r0 + half * 8;
                float v0 = acc[mi][ni][half * 2 + 0] + b0;
                float v1 = acc[mi][ni][half * 2 + 1] + b1;
                if (OUT == 0) {
                    *(float2*)(C + (size_t)r * N + col) = make_float2(v0, v1);
                } else {
                    if (OUT == 1) {
                        v0 *= normcdff(v0);
                        v1 *= normcdff(v1);
                    }
                    u16 h0 = fp_hi(v0), h1 = fp_hi(v1);
                    *(u32*)(Ch + (size_t)r * N + col) = (u32)h0 | ((u32)h1 << 16);
                }
            }
        }
    }
}

// ---------------- tensor-core flash attention (causal, fp16 1-term), qkv split K|Q|V ----------------
// S = Q K^T ; O = P V. 256 threads, 128 queries/CTA, heavy-first.
// 3-stage K/V ring, single sync per tile. smem: Q(16K) | 3 x { K(8K) V(8K) } = 64 KB
#define ATT_STAGE 16384
#define ATT_SMEM (16384 + 3 * ATT_STAGE)   // 64 KB

__global__ __launch_bounds__(256, 2) void attn_mma(
    const u16* __restrict__ qkvh, u16* __restrict__ yh)
{
    extern __shared__ char smem_raw[];
    const uint32_t sb = smem_u32(smem_raw);
    const int tid = threadIdx.x, lane = tid & 31, wid = tid >> 5;
    const int qt = gridDim.x - 1 - blockIdx.x;   // heavy tiles first
    const int h = blockIdx.y, b = blockIdx.z;
    const int q0 = qt * 128;
    const int gid = lane >> 2, qp = lane & 3;
    const size_t tokbase = (size_t)b * SEQ;
    const int rs = 3 * CDIM;

    // Q load (128 rows) — rides in stage-0 commit group
    #pragma unroll
    for (int i = 0; i < 4; ++i) {
        const int idx = i * 256 + tid;
        const int row = idx >> 3, seg = idx & 7;
        const uint32_t off = swz((uint32_t)(row * 128 + seg * 16));
        const size_t g = (tokbase + q0 + row) * rs + CDIM + h * HDIM + seg * 8;
        cp16(sb + off, qkvh + g);
    }

    auto load_stage = [&](int t) {
        const uint32_t st = sb + 16384 + (uint32_t)(t % 3) * ATT_STAGE;
        const int k0 = t * 64;
        #pragma unroll
        for (int i = 0; i < 2; ++i) {
            const int idx = i * 256 + tid;
            const int row = idx >> 3, seg = idx & 7;
            const uint32_t off = swz((uint32_t)(row * 128 + seg * 16));
            const size_t gk = (tokbase + k0 + row) * rs + h * HDIM + seg * 8;
            cp16(st + off,        qkvh + gk);            // K at ch 0
            cp16(st + 8192 + off, qkvh + gk + 2 * CDIM); // V at ch 2C
        }
        CP_COMMIT();
    };

    const int ntiles = 2 * qt + 2;
    load_stage(0);
    if (ntiles > 1) load_stage(1);

    float m0 = -INFINITY, m1 = -INFINITY, l0 = 0.f, l1 = 0.f;
    float oacc[8][4];
    #pragma unroll
    for (int ni = 0; ni < 8; ++ni)
        #pragma unroll
        for (int j = 0; j < 4; ++j) oacc[ni][j] = 0.f;

    const int lr = lane & 15, ck = lane >> 4;
    const int wrow0 = q0 + wid * 16;

    for (int t = 0; t < ntiles; ++t) {
        if (t == ntiles - 1) CP_WAIT(0); else CP_WAIT(1);
        __syncthreads();
        if (t + 2 < ntiles) load_stage(t + 2);
        const uint32_t st = sb + 16384 + (uint32_t)(t % 3) * ATT_STAGE;
        const int k0 = t * 64;
        const bool active = (k0 <= wrow0 + 15);

        if (active) {
            float sacc[8][4];
            #pragma unroll
            for (int ni = 0; ni < 8; ++ni)
                #pragma unroll
                for (int j = 0; j < 4; ++j) sacc[ni][j] = 0.f;

            #pragma unroll
            for (int s = 0; s < 4; ++s) {
                const int c16 = s * 2 + ck;
                u32 aQ[4];
                {
                    const uint32_t off = swz((uint32_t)((wid * 16 + lr) * 128 + c16 * 16));
                    ldsm4(aQ, sb + off);
                }
                u32 bK[8][2];
                #pragma unroll
                for (int ng = 0; ng < 4; ++ng) {
                    const uint32_t off = swz((uint32_t)((ng * 16 + lr) * 128 + c16 * 16));
                    u32 r[4];
                    ldsm4(r, st + off);
                    bK[2 * ng][0] = r[0]; bK[2 * ng + 1][0] = r[1];
                    bK[2 * ng][1] = r[2]; bK[2 * ng + 1][1] = r[3];
                }
                #pragma unroll
                for (int ni = 0; ni < 8; ++ni)
                    mma_fp16(sacc[ni], aQ, bK[ni]);
            }
            #pragma unroll
            for (int ni = 0; ni < 8; ++ni)
                #pragma unroll
                for (int j = 0; j < 4; ++j) sacc[ni][j] *= 0.125f;

            if (k0 + 63 > wrow0) {
                #pragma unroll
                for (int ni = 0; ni < 8; ++ni) {
                    const int kbase = k0 + ni * 8 + qp * 2;
                    #pragma unroll
                    for (int j = 0; j < 4; ++j) {
                        if (kbase + (j & 1) > wrow0 + gid + (j >> 1) * 8) sacc[ni][j] = -INFINITY;
                    }
                }
            }

            float mt0 = -INFINITY, mt1 = -INFINITY;
            #pragma unroll
            for (int ni = 0; ni < 8; ++ni) {
                mt0 = fmaxf(mt0, fmaxf(sacc[ni][0], sacc[ni][1]));
                mt1 = fmaxf(mt1, fmaxf(sacc[ni][2], sacc[ni][3]));
            }
            mt0 = fmaxf(mt0, __shfl_xor_sync(0xffffffffu, mt0, 1));
            mt0 = fmaxf(mt0, __shfl_xor_sync(0xffffffffu, mt0, 2));
            mt1 = fmaxf(mt1, __shfl_xor_sync(0xffffffffu, mt1, 1));
            mt1 = fmaxf(mt1, __shfl_xor_sync(0xffffffffu, mt1, 2));
            const float mn0 = fmaxf(m0, mt0), mn1 = fmaxf(m1, mt1);
            const float sc0 = __expf(m0 - mn0), sc1 = __expf(m1 - mn1);
            m0 = mn0; m1 = mn1;
            float ls0 = 0.f, ls1 = 0.f;
            #pragma unroll
            for (int ni = 0; ni < 8; ++ni) {
                sacc[ni][0] = __expf(sacc[ni][0] - mn0);
                sacc[ni][1] = __expf(sacc[ni][1] - mn0);
                sacc[ni][2] = __expf(sacc[ni][2] - mn1);
                sacc[ni][3] = __expf(sacc[ni][3] - mn1);
                ls0 += sacc[ni][0] + sacc[ni][1];
                ls1 += sacc[ni][2] + sacc[ni][3];
            }
            ls0 += __shfl_xor_sync(0xffffffffu, ls0, 1);
            ls0 += __shfl_xor_sync(0xffffffffu, ls0, 2);
            ls1 += __shfl_xor_sync(0xffffffffu, ls1, 1);
            ls1 += __shfl_xor_sync(0xffffffffu, ls1, 2);
            l0 = l0 * sc0 + ls0;
            l1 = l1 * sc1 + ls1;
            #pragma unroll
            for (int ni = 0; ni < 8; ++ni) {
                oacc[ni][0] *= sc0; oacc[ni][1] *= sc0;
                oacc[ni][2] *= sc1; oacc[ni][3] *= sc1;
            }

            // pack P (fp16)
            u32 aP[4][4];
            #pragma unroll
            for (int s = 0; s < 4; ++s) {
                #pragma unroll
                for (int half = 0; half < 2; ++half) {
                    const float p0 = sacc[2 * s + half][0], p1 = sacc[2 * s + half][1];
                    const float p2 = sacc[2 * s + half][2], p3 = sacc[2 * s + half][3];
                    const u16 h0 = fp_hi(p0), h1 = fp_hi(p1), h2 = fp_hi(p2), h3 = fp_hi(p3);
                    aP[s][half * 2 + 0] = (u32)h0 | ((u32)h1 << 16);
                    aP[s][half * 2 + 1] = (u32)h2 | ((u32)h3 << 16);
                }
            }

            // O += P V
            #pragma unroll
            for (int s = 0; s < 4; ++s) {
                u32 bV[8][2];
                #pragma unroll
                for (int nd = 0; nd < 4; ++nd) {
                    const uint32_t off = swz((uint32_t)((s * 16 + lr) * 128 + nd * 32 + ck * 16));
                    u32 r[4];
                    ldsm4t(r, st + 8192 + off);
                    bV[2 * nd][0] = r[0]; bV[2 * nd][1] = r[1];
                    bV[2 * nd + 1][0] = r[2]; bV[2 * nd + 1][1] = r[3];
                }
                #pragma unroll
                for (int ni = 0; ni < 8; ++ni)
                    mma_fp16(oacc[ni], aP[s], bV[ni]);
            }
        }
    }

    const float rl0 = 1.f / l0, rl1 = 1.f / l1;
    const int r0 = wrow0 + gid, r1 = r0 + 8;
    #pragma unroll
    for (int ni = 0; ni < 8; ++ni) {
        const int col = h * HDIM + ni * 8 + qp * 2;
        {
            const float v0 = oacc[ni][0] * rl0, v1 = oacc[ni][1] * rl0;
            const u16 h0 = fp_hi(v0), h1 = fp_hi(v1);
            *(u32*)(yh + (tokbase + r0) * CDIM + col) = (u32)h0 | ((u32)h1 << 16);
        }
        {
            const float v0 = oacc[ni][2] * rl1, v1 = oacc[ni][3] * rl1;
            const u16 h0 = fp_hi(v0), h1 = fp_hi(v1);
            *(u32*)(yh + (tokbase + r1) * CDIM + col) = (u32)h0 | ((u32)h1 << 16);
        }
    }
}

// ---------------- residual + LayerNorm ----------------
__device__ __forceinline__ float block_sum256(float v, float* red) {
    const int lane = threadIdx.x & 31;
    const int w = threadIdx.x >> 5;
    #pragma unroll
    for (int off = 16; off; off >>= 1) v += __shfl_xor_sync(0xffffffffu, v, off);
    if (lane == 0) red[w] = v;
    __syncthreads();
    float t = (threadIdx.x < 8) ? red[threadIdx.x] : 0.f;
    if (w == 0) {
        t += __shfl_xor_sync(0xffffffffu, t, 4);
        t += __shfl_xor_sync(0xffffffffu, t, 2);
        t += __shfl_xor_sync(0xffffffffu, t, 1);
        if (lane == 0) red[0] = t;
    }
    __syncthreads();
    const float r = red[0];
    __syncthreads();
    return r;
}

template<bool PAIR>
__global__ __launch_bounds__(256) void add_ln_kernel(
    const float* __restrict__ xres, const float* __restrict__ v,
    const float* __restrict__ g, const float* __restrict__ be,
    float* __restrict__ out, u16* __restrict__ oh)
{
    __shared__ float red[8];
    const size_t row = blockIdx.x;
    const int c0 = threadIdx.x * 4;
    const float* vr = v + row * CDIM;

    float vals[4];
    *(float4*)vals = *(const float4*)(vr + c0);
    float s = vals[0] + vals[1] + vals[2] + vals[3];
    const float mean = block_sum256(s, red) * (1.f / CDIM);

    float d2 = 0.f;
    #pragma unroll
    for (int i = 0; i < 4; ++i) {
        const float d = vals[i] - mean;
        d2 = fmaf(d, d, d2);
    }
    const float var = block_sum256(d2, red) * (1.f / CDIM);
    const float rstd = rsqrtf(var + 1e-5f);

    float4 xr = *(const float4*)(xres + row * CDIM + c0);
    float4 gg = *(const float4*)(g + c0);
    float4 bb = *(const float4*)(be + c0);
    float4 res;
    res.x = xr.x + (vals[0] - mean) * rstd * gg.x + bb.x;
    res.y = xr.y + (vals[1] - mean) * rstd * gg.y + bb.y;
    res.z = xr.z + (vals[2] - mean) * rstd * gg.z + bb.z;
    res.w = xr.w + (vals[3] - mean) * rstd * gg.w + bb.w;
    *(float4*)(out + row * CDIM + c0) = res;
    if (PAIR) {
        u16 h0 = fp_hi(res.x), h1 = fp_hi(res.y), h2 = fp_hi(res.z), h3 = fp_hi(res.w);
        *(uint2*)(oh + row * CDIM + c0) =
            make_uint2((u32)h0 | ((u32)h1 << 16), (u32)h2 | ((u32)h3 << 16));
    }
}

// ---------------- launch ----------------
extern "C" void kernel_launch(void* const* d_in, const int* in_sizes, int n_in,
                              void* d_out, int out_size)
{
    const float* x      = (const float*)d_in[0];
    const float* w_attn = (const float*)d_in[1];
    const float* b_attn = (const float*)d_in[2];
    const float* wa1    = (const float*)d_in[3];
    const float* ba1    = (const float*)d_in[4];
    const float* wa2    = (const float*)d_in[5];
    const float* ba2    = (const float*)d_in[6];
    const float* g1     = (const float*)d_in[7];
    const float* be1    = (const float*)d_in[8];
    const float* wf1    = (const float*)d_in[9];
    const float* bf1    = (const float*)d_in[10];
    const float* wf2    = (const float*)d_in[11];
    const float* bf2    = (const float*)d_in[12];
    const float* g2     = (const float*)d_in[13];
    const float* be2    = (const float*)d_in[14];
    float* out = (float*)d_out;

    float *tbuf, *x1;
    u16 *xh, *qkvh, *yh, *x1h, *hh;
    u16 *wa, *w1, *w2, *w3, *w4;
    cudaGetSymbolAddress((void**)&tbuf, g_t);
    cudaGetSymbolAddress((void**)&x1, g_x1);
    cudaGetSymbolAddress((void**)&xh, g_xh);
    cudaGetSymbolAddress((void**)&qkvh, g_qkvh);
    cudaGetSymbolAddress((void**)&yh, g_yh);
    cudaGetSymbolAddress((void**)&x1h, g_x1h);
    cudaGetSymbolAddress((void**)&hh, g_hh);
    cudaGetSymbolAddress((void**)&wa, g_wa);
    cudaGetSymbolAddress((void**)&w1, g_w1);
    cudaGetSymbolAddress((void**)&w2, g_w2);
    cudaGetSymbolAddress((void**)&w3, g_w3);
    cudaGetSymbolAddress((void**)&w4, g_w4);

    cudaFuncSetAttribute(mma_gemm<0>, cudaFuncAttributeMaxDynamicSharedMemorySize, MG_SMEM);
    cudaFuncSetAttribute(mma_gemm<1>, cudaFuncAttributeMaxDynamicSharedMemorySize, MG_SMEM);
    cudaFuncSetAttribute(mma_gemm<2>, cudaFuncAttributeMaxDynamicSharedMemorySize, MG_SMEM);
    cudaFuncSetAttribute(attn_mma, cudaFuncAttributeMaxDynamicSharedMemorySize, ATT_SMEM);

    // fork-join side stream for prep work (graph-capture-safe pattern)
    cudaStream_t s2;
    cudaEvent_t eFork, eConv, eW;
    cudaStreamCreateWithFlags(&s2, cudaStreamNonBlocking);
    cudaEventCreateWithFlags(&eFork, cudaEventDisableTiming);
    cudaEventCreateWithFlags(&eConv, cudaEventDisableTiming);
    cudaEventCreateWithFlags(&eW, cudaEventDisableTiming);

    const dim3 tb(32, 8);

    // fork
    cudaEventRecord(eFork, 0);
    cudaStreamWaitEvent(s2, eFork, 0);

    // side stream: x conversion, then w1..w4 transposes
    conv_k<<<(ROWS * CDIM / 4 + 255) / 256, 256, 0, s2>>>(x, xh, ROWS * CDIM / 4);
    cudaEventRecord(eConv, s2);
    tdecomp_k<<<dim3(HID / 32, CDIM / 32), tb, 0, s2>>>(wa1, w1, CDIM, HID);
    tdecomp_k<<<dim3(CDIM / 32, HID / 32), tb, 0, s2>>>(wa2, w2, HID, CDIM);
    tdecomp_k<<<dim3(HID / 32, CDIM / 32), tb, 0, s2>>>(wf1, w3, CDIM, HID);
    tdecomp_k<<<dim3(CDIM / 32, HID / 32), tb, 0, s2>>>(wf2, w4, HID, CDIM);
    cudaEventRecord(eW, s2);

    // main stream: wa transpose concurrent with conv_k
    tdecomp_k<<<dim3(3 * CDIM / 32, CDIM / 32), tb>>>(w_attn, wa, CDIM, 3 * CDIM);
    cudaStreamWaitEvent(0, eConv, 0);

    // qkv = x @ w_attn + b_attn -> fp16
    mma_gemm<2><<<dim3(3 * CDIM / 128, ROWS / 128), 256, MG_SMEM>>>(
        xh, wa, b_attn, nullptr, qkvh, 3 * CDIM, CDIM);

    // causal MHA -> y
    attn_mma<<<dim3(SEQ / 128, NHEAD, BATCH), 256, ATT_SMEM>>>(qkvh, yh);

    cudaStreamWaitEvent(0, eW, 0);

    // h = gelu(y @ wa1 + ba1)
    mma_gemm<1><<<dim3(HID / 128, ROWS / 128), 256, MG_SMEM>>>(
        yh, w1, ba1, nullptr, hh, HID, CDIM);

    // t = h @ wa2 + ba2 (fp32)
    mma_gemm<0><<<dim3(CDIM / 128, ROWS / 128), 256, MG_SMEM>>>(
        hh, w2, ba2, tbuf, nullptr, CDIM, HID);

    // x1 = x + LN(t)
    add_ln_kernel<true><<<ROWS, 256>>>(x, tbuf, g1, be1, x1, x1h);

    // h = gelu(x1 @ wf1 + bf1)
    mma_gemm<1><<<dim3(HID / 128, ROWS / 128), 256, MG_SMEM>>>(
        x1h, w3, bf1, nullptr, hh, HID, CDIM);

    // t = h @ wf2 + bf2 (fp32)
    mma_gemm<0><<<dim3(CDIM / 128, ROWS / 128), 256, MG_SMEM>>>(
        hh, w4, bf2, tbuf, nullptr, CDIM, HID);

    // out = x1 + LN(t)
    add_ln_kernel<false><<<ROWS, 256>>>(x1, tbuf, g2, be2, out, nullptr);

    cudaStreamDestroy(s2);
    cudaEventDestroy(eFork);
    cudaEventDestroy(eConv);
    cudaEventDestroy(eW);
}